// round 2
// baseline (speedup 1.0000x reference)
#include <cuda_runtime.h>
#include <math.h>
#include <stdint.h>

// ---------------- constants ----------------
#define BB 64
#define TT 20
#define EE 300
#define CEE 1024
#define ANSN 3000
#define HH 512
#define NN 256
#define WW 64
#define RR 4
#define RWRW 256       // R*W
#define IFTOT 471
#define CLIPV 20.0f
#define EPSV 1e-6f

// state offsets inside g_state
#define OFF_MEM    0            // B*N*W = 1048576
#define OFF_LINK   1048576      // B*N*N = 4194304
#define OFF_PREC   5242880      // B*N
#define OFF_WR     5259264      // B*R*N = 65536
#define OFF_WW     5324800      // B*N
#define OFF_USAGE  5341184      // B*N
#define OFF_RVEC   5357568      // B*R*W = 16384
#define OFF_H      5373952      // B*H = 32768
#define OFF_C      5406720      // B*H
#define STATE_TOT  5439488

// ---------------- device globals (scratch; no allocation allowed) ----------------
__device__ float g_state[STATE_TOT];
__device__ float g_qv[BB * TT * EE];
__device__ float g_gates[BB * 4 * HH];
__device__ float g_hc[BB * HH];
__device__ float g_xi[BB * IFTOT];
__device__ float g_rkeys[BB * RR * WW];
__device__ float g_rstr[BB * RR];
__device__ float g_wkey[BB * WW];
__device__ float g_wstr[BB];
__device__ float g_erase[BB * WW];
__device__ float g_wvec[BB * WW];
__device__ float g_free[BB * RR];
__device__ float g_allocg[BB];
__device__ float g_writeg[BB];
__device__ float g_modes[BB * RR * 3];
__device__ float g_alloc[BB * NN];
__device__ float g_wwsum[BB];
__device__ float g_fw[BB * RR * NN];
__device__ float g_bw[BB * RR * NN];
__device__ float g_cr[BB * RR * NN];
__device__ float g_outbuf[BB * CEE];
__device__ float g_qsum[BB * CEE];
__device__ float g_imgf[BB * CEE];
__device__ float g_comb[BB * CEE];
__device__ float g_last[BB * (CEE + RWRW)];
__device__ float g_fc1[BB * ANSN];

// ---------------- helpers ----------------
__device__ __forceinline__ float sigf(float x) { return 1.0f / (1.0f + expf(-x)); }
__device__ __forceinline__ float softplusf(float x) {
    return fmaxf(x, 0.0f) + log1pf(expf(-fabsf(x)));
}

__device__ __forceinline__ float blk_max(float v, volatile float* red, int tid) {
    red[tid] = v; __syncthreads();
    for (int s = 128; s > 0; s >>= 1) {
        if (tid < s) red[tid] = fmaxf((float)red[tid], (float)red[tid + s]);
        __syncthreads();
    }
    float r = red[0]; __syncthreads();
    return r;
}
__device__ __forceinline__ float blk_sum(float v, volatile float* red, int tid) {
    red[tid] = v; __syncthreads();
    for (int s = 128; s > 0; s >>= 1) {
        if (tid < s) red[tid] = (float)red[tid] + (float)red[tid + s];
        __syncthreads();
    }
    float r = red[0]; __syncthreads();
    return r;
}

// ---------------- generic kernels ----------------
__global__ void k_zero(float* p, int n) {
    int i = blockIdx.x * blockDim.x + threadIdx.x;
    if (i < n) p[i] = 0.0f;
}

__global__ void k_embed(const int* __restrict__ qst, const float* __restrict__ emb) {
    int i = blockIdx.x * blockDim.x + threadIdx.x;
    if (i >= BB * TT * EE) return;
    int e = i % EE;
    int bt = i / EE;           // b*T + t
    int tok = qst[bt];
    g_qv[i] = tanhf(emb[(size_t)tok * EE + e]);
}

// C[64,Nout] = concat(A0,A1,A2) @ concat(W0,W1,W2) + bias, optional act, optional accumulate
// act: 0 none, 1 clip+-20, 2 tanh
__global__ void gemm3(const float* __restrict__ A0, const float* __restrict__ W0, int K0, int lda0,
                      const float* __restrict__ A1, const float* __restrict__ W1, int K1, int lda1,
                      const float* __restrict__ A2, const float* __restrict__ W2, int K2, int lda2,
                      const float* __restrict__ bias, float* __restrict__ C,
                      float* __restrict__ accum, int Nout, int act) {
    __shared__ __align__(16) float As[16][17];
    __shared__ __align__(16) float Ws[16][66];
    int tid = threadIdx.x;
    int tx = tid & 31;     // 0..31 (col pair)
    int ty = tid >> 5;     // 0..7 (row pair)
    int col0 = blockIdx.x * 64;
    int row0 = blockIdx.y * 16;
    float acc00 = 0, acc01 = 0, acc10 = 0, acc11 = 0;

    const float* Aarr[3] = {A0, A1, A2};
    const float* Warr[3] = {W0, W1, W2};
    int Karr[3] = {K0, K1, K2};
    int Larr[3] = {lda0, lda1, lda2};

    for (int s = 0; s < 3; s++) {
        const float* A = Aarr[s];
        const float* Wt = Warr[s];
        int K = Karr[s];
        int lda = Larr[s];
        if (K == 0 || A == 0) continue;
        for (int k0 = 0; k0 < K; k0 += 16) {
            {   // load A tile: 16 rows x 16 k
                int r = tid >> 4, kk = tid & 15;
                int k = k0 + kk;
                As[r][kk] = (k < K) ? A[(size_t)(row0 + r) * lda + k] : 0.0f;
            }
            {   // load W tile: 16 k x 64 cols
                int kk = tid >> 4;
                int cb = (tid & 15) * 4;
                int k = k0 + kk;
#pragma unroll
                for (int u = 0; u < 4; u++) {
                    int c = col0 + cb + u;
                    Ws[kk][cb + u] = (k < K && c < Nout) ? Wt[(size_t)k * Nout + c] : 0.0f;
                }
            }
            __syncthreads();
#pragma unroll
            for (int kk = 0; kk < 16; kk++) {
                float a0 = As[ty * 2][kk];
                float a1 = As[ty * 2 + 1][kk];
                float2 bv = *(const float2*)&Ws[kk][tx * 2];
                acc00 += a0 * bv.x; acc01 += a0 * bv.y;
                acc10 += a1 * bv.x; acc11 += a1 * bv.y;
            }
            __syncthreads();
        }
    }
    float vs[2][2] = {{acc00, acc01}, {acc10, acc11}};
#pragma unroll
    for (int i = 0; i < 2; i++) {
        int row = row0 + ty * 2 + i;
#pragma unroll
        for (int j = 0; j < 2; j++) {
            int c = col0 + tx * 2 + j;
            if (c < Nout) {
                float v = vs[i][j] + bias[c];
                if (act == 1) v = fminf(fmaxf(v, -CLIPV), CLIPV);
                else if (act == 2) v = tanhf(v);
                C[(size_t)row * Nout + c] = v;
                if (accum) accum[(size_t)row * Nout + c] += v;
            }
        }
    }
}

__global__ void k_lstm() {
    int idx = blockIdx.x * blockDim.x + threadIdx.x;
    if (idx >= BB * HH) return;
    int b = idx >> 9;
    int j = idx & 511;
    int base = b * 4 * HH;
    float gi = g_gates[base + j];
    float gf = g_gates[base + HH + j];
    float gg = g_gates[base + 2 * HH + j];
    float go = g_gates[base + 3 * HH + j];
    float cc = sigf(gf) * g_state[OFF_C + idx] + sigf(gi) * tanhf(gg);
    float hh = sigf(go) * tanhf(cc);
    g_state[OFF_C + idx] = cc;
    g_state[OFF_H + idx] = hh;
    g_hc[idx] = fminf(fmaxf(hh, -CLIPV), CLIPV);
}

__global__ void k_iface() {
    int b = blockIdx.x;
    int t = threadIdx.x;
    if (t >= IFTOT) return;
    float v = g_xi[b * IFTOT + t];
    if (t < 256) {
        g_rkeys[b * 256 + t] = tanhf(v);
    } else if (t < 260) {
        g_rstr[b * 4 + (t - 256)] = softplusf(v);
    } else if (t < 324) {
        g_wkey[b * 64 + (t - 260)] = tanhf(v);
    } else if (t == 324) {
        g_wstr[b] = softplusf(v);
    } else if (t < 389) {
        g_erase[b * 64 + (t - 325)] = sigf(v);
    } else if (t < 453) {
        g_wvec[b * 64 + (t - 389)] = tanhf(v);
    } else if (t < 457) {
        g_free[b * 4 + (t - 453)] = sigf(v);
    } else if (t == 457) {
        g_allocg[b] = sigf(v);
    } else if (t == 458) {
        g_writeg[b] = sigf(v);
    } else {
        int i = t - 459;      // 0..11
        int r = i / 3;
        float v0 = g_xi[b * IFTOT + 459 + r * 3 + 0];
        float v1 = g_xi[b * IFTOT + 459 + r * 3 + 1];
        float v2 = g_xi[b * IFTOT + 459 + r * 3 + 2];
        float m = fmaxf(v0, fmaxf(v1, v2));
        float e0 = expf(v0 - m), e1 = expf(v1 - m), e2 = expf(v2 - m);
        float s = e0 + e1 + e2;
        float sel = (i % 3 == 0) ? e0 : ((i % 3 == 1) ? e1 : e2);
        g_modes[b * 12 + i] = sel / s;
    }
}

// usage update + stable argsort + cumprod allocation (one block per batch row)
__global__ void k_usage_alloc() {
    __shared__ float sv[256];
    __shared__ int si[256];
    __shared__ float sc[256];
    int b = blockIdx.x;
    int tid = threadIdx.x;

    float psi = 1.0f;
#pragma unroll
    for (int r = 0; r < RR; r++)
        psi *= 1.0f - g_free[b * 4 + r] * g_state[OFF_WR + b * 1024 + r * 256 + tid];
    float uo = g_state[OFF_USAGE + b * 256 + tid];
    float wo = g_state[OFF_WW + b * 256 + tid];
    float u = (uo + wo - uo * wo) * psi;
    g_state[OFF_USAGE + b * 256 + tid] = u;

    sv[tid] = u; si[tid] = tid;
    __syncthreads();
    // bitonic ascending on (value, index) -> stable argsort
    for (int k = 2; k <= 256; k <<= 1) {
        for (int j = k >> 1; j > 0; j >>= 1) {
            int ixj = tid ^ j;
            if (ixj > tid) {
                float v1 = sv[tid], v2 = sv[ixj];
                int i1 = si[tid], i2 = si[ixj];
                bool up = ((tid & k) == 0);
                bool gt = (v1 > v2) || (v1 == v2 && i1 > i2);
                bool doswap = up ? gt : !gt;
                if (doswap) { sv[tid] = v2; sv[ixj] = v1; si[tid] = i2; si[ixj] = i1; }
            }
            __syncthreads();
        }
    }
    // inclusive product scan
    sc[tid] = sv[tid];
    __syncthreads();
    for (int off = 1; off < 256; off <<= 1) {
        float tval = (tid >= off) ? sc[tid - off] : 1.0f;
        __syncthreads();
        sc[tid] *= tval;
        __syncthreads();
    }
    float cpe = (tid == 0) ? 1.0f : sc[tid - 1];
    g_alloc[b * 256 + si[tid]] = (1.0f - sv[tid]) * cpe;
}

// write content weights + final ww + wwsum (one block per batch)
__global__ void k_write_ww() {
    __shared__ float key[64];
    __shared__ float red[256];
    int b = blockIdx.x;
    int tid = threadIdx.x;
    if (tid < 64) key[tid] = g_wkey[b * 64 + tid];
    __syncthreads();
    float kn = 0;
#pragma unroll
    for (int w = 0; w < 64; w++) kn += key[w] * key[w];
    kn = sqrtf(kn) + EPSV;
    float dot = 0, mn = 0;
    size_t base = (size_t)OFF_MEM + (size_t)b * NN * WW + (size_t)tid * WW;
#pragma unroll 8
    for (int w = 0; w < 64; w++) {
        float m = g_state[base + w];
        dot += m * key[w];
        mn += m * m;
    }
    float sim = g_wstr[b] * dot / ((sqrtf(mn) + EPSV) * kn);
    float mx = blk_max(sim, red, tid);
    float e = expf(sim - mx);
    float sm = blk_sum(e, red, tid);
    float cwv = e / sm;
    float ag = g_allocg[b], wg = g_writeg[b];
    float wwv = wg * (ag * g_alloc[b * 256 + tid] + (1.0f - ag) * cwv);
    g_state[OFF_WW + b * 256 + tid] = wwv;
    float s2 = blk_sum(wwv, red, tid);
    if (tid == 0) g_wwsum[b] = s2;
}

__global__ void k_memupd() {
    int idx = blockIdx.x * blockDim.x + threadIdx.x;
    if (idx >= BB * NN * WW) return;
    int w = idx & 63;
    int n = (idx >> 6) & 255;
    int b = idx >> 14;
    float wwv = g_state[OFF_WW + b * 256 + n];
    float m = g_state[OFF_MEM + idx];
    g_state[OFF_MEM + idx] = m * (1.0f - wwv * g_erase[b * 64 + w]) + wwv * g_wvec[b * 64 + w];
}

__global__ void k_link() {
    int idx = blockIdx.x * blockDim.x + threadIdx.x;
    if (idx >= BB * NN * NN) return;
    int j = idx & 255;
    int i = (idx >> 8) & 255;
    int b = idx >> 16;
    float wi = g_state[OFF_WW + b * 256 + i];
    float wj = g_state[OFF_WW + b * 256 + j];
    float v;
    if (i == j) v = 0.0f;
    else v = (1.0f - wi - wj) * g_state[OFF_LINK + idx] + wi * g_state[OFF_PREC + b * 256 + j];
    g_state[OFF_LINK + idx] = v;
}

__global__ void k_prec() {
    int idx = blockIdx.x * blockDim.x + threadIdx.x;
    if (idx >= BB * NN) return;
    int b = idx >> 8;
    g_state[OFF_PREC + idx] = (1.0f - g_wwsum[b]) * g_state[OFF_PREC + idx] + g_state[OFF_WW + idx];
}

// fw[b,r,i] = sum_j link[b,i,j] * wr_old[b,r,j]  (warp per (b,i))
__global__ void k_fw() {
    int tid = threadIdx.x;
    int lane = tid & 31;
    int warp = blockIdx.x * 8 + (tid >> 5);   // 0..16383
    int b = warp >> 8;
    int i = warp & 255;
    size_t base = (size_t)OFF_LINK + (size_t)b * 65536 + (size_t)i * 256;
    float acc[4] = {0, 0, 0, 0};
#pragma unroll
    for (int kk = 0; kk < 8; kk++) {
        int jj = lane + kk * 32;
        float lv = g_state[base + jj];
#pragma unroll
        for (int r = 0; r < 4; r++)
            acc[r] += lv * g_state[OFF_WR + b * 1024 + r * 256 + jj];
    }
#pragma unroll
    for (int r = 0; r < 4; r++) {
#pragma unroll
        for (int off = 16; off > 0; off >>= 1)
            acc[r] += __shfl_xor_sync(0xffffffff, acc[r], off);
    }
    if (lane == 0) {
#pragma unroll
        for (int r = 0; r < 4; r++)
            g_fw[b * 1024 + r * 256 + i] = acc[r];
    }
}

// bw[b,r,i] = sum_j link[b,j,i] * wr_old[b,r,j]  (block per b, accumulate over rows)
__global__ void k_bw() {
    __shared__ float wrs[4][256];
    __shared__ float Lt[8][256];
    int b = blockIdx.x;
    int tid = threadIdx.x;
#pragma unroll
    for (int r = 0; r < 4; r++) wrs[r][tid] = g_state[OFF_WR + b * 1024 + r * 256 + tid];
    __syncthreads();
    float acc[4] = {0, 0, 0, 0};
    for (int jt = 0; jt < 32; jt++) {
#pragma unroll
        for (int u = 0; u < 8; u++)
            Lt[u][tid] = g_state[(size_t)OFF_LINK + (size_t)b * 65536 + (size_t)(jt * 8 + u) * 256 + tid];
        __syncthreads();
#pragma unroll
        for (int u = 0; u < 8; u++) {
            int jj = jt * 8 + u;
            float lv = Lt[u][tid];
#pragma unroll
            for (int r = 0; r < 4; r++) acc[r] += wrs[r][jj] * lv;
        }
        __syncthreads();
    }
#pragma unroll
    for (int r = 0; r < 4; r++) g_bw[b * 1024 + r * 256 + tid] = acc[r];
}

// read content weights (block per b; uses NEW mem)
__global__ void k_cr() {
    __shared__ float keys[4][64];
    __shared__ float knorm[4];
    __shared__ float rstr[4];
    __shared__ float red[256];
    int b = blockIdx.x;
    int tid = threadIdx.x;
    keys[tid >> 6][tid & 63] = g_rkeys[b * 256 + tid];
    __syncthreads();
    if (tid < 4) {
        float s = 0;
#pragma unroll
        for (int w = 0; w < 64; w++) s += keys[tid][w] * keys[tid][w];
        knorm[tid] = sqrtf(s) + EPSV;
        rstr[tid] = g_rstr[b * 4 + tid];
    }
    __syncthreads();
    float mn = 0;
    float dots[4] = {0, 0, 0, 0};
    size_t base = (size_t)OFF_MEM + (size_t)b * NN * WW + (size_t)tid * WW;
#pragma unroll 4
    for (int w = 0; w < 64; w++) {
        float m = g_state[base + w];
        mn += m * m;
#pragma unroll
        for (int r = 0; r < 4; r++) dots[r] += m * keys[r][w];
    }
    float mnorm = sqrtf(mn) + EPSV;
    float sim[4];
#pragma unroll
    for (int r = 0; r < 4; r++) sim[r] = rstr[r] * dots[r] / (mnorm * knorm[r]);
    for (int r = 0; r < 4; r++) {
        float mx = blk_max(sim[r], red, tid);
        float e = expf(sim[r] - mx);
        float sm = blk_sum(e, red, tid);
        g_cr[b * 1024 + r * 256 + tid] = e / sm;
    }
}

// wr update + rvec (block per b)
__global__ void k_wr_rvec() {
    __shared__ float ws[4][256];
    int b = blockIdx.x;
    int tid = threadIdx.x;
#pragma unroll
    for (int r = 0; r < 4; r++) {
        float m0 = g_modes[b * 12 + r * 3 + 0];
        float m1 = g_modes[b * 12 + r * 3 + 1];
        float m2 = g_modes[b * 12 + r * 3 + 2];
        float v = m0 * g_bw[b * 1024 + r * 256 + tid]
                + m1 * g_cr[b * 1024 + r * 256 + tid]
                + m2 * g_fw[b * 1024 + r * 256 + tid];
        g_state[OFF_WR + b * 1024 + r * 256 + tid] = v;
        ws[r][tid] = v;
    }
    __syncthreads();
    int r2 = tid >> 6;
    int w = tid & 63;
    float acc = 0;
    size_t mbase = (size_t)OFF_MEM + (size_t)b * NN * WW;
    for (int n = 0; n < 256; n++)
        acc += ws[r2][n] * g_state[mbase + (size_t)n * 64 + w];
    g_state[OFF_RVEC + b * 256 + tid] = acc;
}

// image normalize + combine with qfeat (=qsum/20)
__global__ void k_comb() {
    __shared__ float red[256];
    int b = blockIdx.x;
    int tid = threadIdx.x;
    float s = 0;
    for (int j = tid; j < CEE; j += 256) {
        float v = g_imgf[b * CEE + j];
        s += v * v;
    }
    float tot = blk_sum(s, red, tid);
    float inv = rsqrtf(tot);
    for (int j = tid; j < CEE; j += 256) {
        float v = g_imgf[b * CEE + j] * inv;
        g_comb[b * CEE + j] = tanhf(v * g_qsum[b * CEE + j] * (1.0f / (float)TT));
    }
}

__global__ void k_last() {
    int idx = blockIdx.x * blockDim.x + threadIdx.x;
    if (idx >= BB * (CEE + RWRW)) return;
    int b = idx / (CEE + RWRW);
    int j = idx % (CEE + RWRW);
    float v = (j < CEE) ? g_outbuf[b * CEE + j] : g_state[OFF_RVEC + b * 256 + (j - CEE)];
    g_last[idx] = tanhf(v);
}

// ---------------- host ----------------
struct Ptrs {
    float *state, *qv, *gates, *hc, *xi, *outbuf, *qsum, *imgf, *comb, *last, *fc1;
};

static void launch_gemm(const float* A0, const float* W0, int K0, int lda0,
                        const float* A1, const float* W1, int K1, int lda1,
                        const float* A2, const float* W2, int K2, int lda2,
                        const float* bias, float* C, float* accum, int Nout, int act) {
    dim3 grid((Nout + 63) / 64, 4);
    gemm3<<<grid, 256>>>(A0, W0, K0, lda0, A1, W1, K1, lda1, A2, W2, K2, lda2,
                         bias, C, accum, Nout, act);
}

static void dnc_step(const Ptrs& P,
                     const float* x, int K0, int lda0,
                     const float* Wih, const float* Whh, const float* bgate,
                     const float* Wif, const float* bif,
                     const float* Wout, const float* bout,
                     float* outC, float* accum) {
    // gates = [x | rvec] @ Wih + h @ Whh + b
    launch_gemm(x, Wih, K0, lda0,
                P.state + OFF_RVEC, Wih + (size_t)K0 * (4 * HH), RWRW, RWRW,
                P.state + OFF_H, Whh, HH, HH,
                bgate, P.gates, 0, 4 * HH, 0);
    k_lstm<<<(BB * HH + 255) / 256, 256>>>();
    launch_gemm(P.hc, Wif, HH, HH, 0, 0, 0, 0, 0, 0, 0, 0, bif, P.xi, 0, IFTOT, 0);
    k_iface<<<BB, 512>>>();
    k_usage_alloc<<<BB, 256>>>();
    k_write_ww<<<BB, 256>>>();
    k_memupd<<<(BB * NN * WW + 255) / 256, 256>>>();
    k_link<<<(BB * NN * NN + 255) / 256, 256>>>();
    k_prec<<<(BB * NN + 255) / 256, 256>>>();
    k_fw<<<BB * NN / 8, 256>>>();
    k_bw<<<BB, 256>>>();
    k_cr<<<BB, 256>>>();
    k_wr_rvec<<<BB, 256>>>();
    // out = [hc | rvec] @ Wout + bout, clip
    launch_gemm(P.hc, Wout, HH, HH,
                P.state + OFF_RVEC, Wout + (size_t)HH * CEE, RWRW, RWRW,
                0, 0, 0, 0,
                bout, outC, accum, CEE, 1);
}

extern "C" void kernel_launch(void* const* d_in, const int* in_sizes, int n_in,
                              void* d_out, int out_size) {
    const float* img_feat = (const float*)d_in[0];
    const int*   qst      = (const int*)d_in[1];
    const float* emb      = (const float*)d_in[2];
    const float* img_W    = (const float*)d_in[3];
    const float* img_b    = (const float*)d_in[4];
    const float* q_Wih    = (const float*)d_in[5];
    const float* q_Whh    = (const float*)d_in[6];
    const float* q_b      = (const float*)d_in[7];
    const float* q_Wif    = (const float*)d_in[8];
    const float* q_bif    = (const float*)d_in[9];
    const float* q_Wout   = (const float*)d_in[10];
    const float* q_bout   = (const float*)d_in[11];
    const float* c_Wih    = (const float*)d_in[12];
    const float* c_Whh    = (const float*)d_in[13];
    const float* c_b      = (const float*)d_in[14];
    const float* c_Wif    = (const float*)d_in[15];
    const float* c_bif    = (const float*)d_in[16];
    const float* c_Wout   = (const float*)d_in[17];
    const float* c_bout   = (const float*)d_in[18];
    const float* fc1_W    = (const float*)d_in[19];
    const float* fc1_b    = (const float*)d_in[20];
    const float* fc2_W    = (const float*)d_in[21];
    const float* fc2_b    = (const float*)d_in[22];
    float* out = (float*)d_out;

    Ptrs P;
    cudaGetSymbolAddress((void**)&P.state, g_state);
    cudaGetSymbolAddress((void**)&P.qv, g_qv);
    cudaGetSymbolAddress((void**)&P.gates, g_gates);
    cudaGetSymbolAddress((void**)&P.hc, g_hc);
    cudaGetSymbolAddress((void**)&P.xi, g_xi);
    cudaGetSymbolAddress((void**)&P.outbuf, g_outbuf);
    cudaGetSymbolAddress((void**)&P.qsum, g_qsum);
    cudaGetSymbolAddress((void**)&P.imgf, g_imgf);
    cudaGetSymbolAddress((void**)&P.comb, g_comb);
    cudaGetSymbolAddress((void**)&P.last, g_last);
    cudaGetSymbolAddress((void**)&P.fc1, g_fc1);

    // zero state + qsum
    k_zero<<<(STATE_TOT + 255) / 256, 256>>>(P.state, STATE_TOT);
    k_zero<<<(BB * CEE + 255) / 256, 256>>>(P.qsum, BB * CEE);

    // question embedding
    k_embed<<<(BB * TT * EE + 255) / 256, 256>>>(qst, emb);

    // question DNC over T timesteps
    for (int t = 0; t < TT; t++) {
        dnc_step(P, P.qv + (size_t)t * EE, EE, TT * EE,
                 q_Wih, q_Whh, q_b, q_Wif, q_bif, q_Wout, q_bout,
                 P.outbuf, P.qsum);
    }

    // image encoder
    launch_gemm(img_feat, img_W, 4096, 4096, 0, 0, 0, 0, 0, 0, 0, 0,
                img_b, P.imgf, 0, CEE, 0);
    k_comb<<<BB, 256>>>();

    // controller DNC: fresh state, single step
    k_zero<<<(STATE_TOT + 255) / 256, 256>>>(P.state, STATE_TOT);
    dnc_step(P, P.comb, CEE, CEE,
             c_Wih, c_Whh, c_b, c_Wif, c_bif, c_Wout, c_bout,
             P.outbuf, 0);

    // tail
    k_last<<<(BB * (CEE + RWRW) + 255) / 256, 256>>>();
    launch_gemm(P.last, fc1_W, CEE + RWRW, CEE + RWRW, 0, 0, 0, 0, 0, 0, 0, 0,
                fc1_b, P.fc1, 0, ANSN, 2);
    launch_gemm(P.fc1, fc2_W, ANSN, ANSN, 0, 0, 0, 0, 0, 0, 0, 0,
                fc2_b, out, 0, ANSN, 0);
}

// round 4
// speedup vs baseline: 1.4958x; 1.4958x over previous
#include <cuda_runtime.h>
#include <math.h>
#include <stdint.h>

// ---------------- constants ----------------
#define BB 64
#define TT 20
#define EE 300
#define CEE 1024
#define ANSN 3000
#define HH 512
#define NN 256
#define WW 64
#define RR 4
#define RWRW 256
#define IFTOT 471
#define CLIPV 20.0f
#define EPSV 1e-6f

// state offsets inside g_state
#define OFF_MEM    0            // B*N*W
#define OFF_LINK   1048576      // B*N*N
#define OFF_PREC   5242880      // B*N
#define OFF_WR     5259264      // B*R*N
#define OFF_WW     5324800      // B*N
#define OFF_USAGE  5341184      // B*N
#define OFF_RVEC   5357568      // B*R*W
#define OFF_H      5373952      // B*H
#define OFF_C      5406720      // B*H
#define STATE_TOT  5439488

// ---------------- device globals ----------------
__device__ float g_state[STATE_TOT];
__device__ float g_qv[BB * TT * EE];
__device__ float g_pre[BB * TT * 2048];       // precomputed x@Wih_x for all timesteps
__device__ float g_part[4 * 64 * 3072];       // split-K partials
__device__ float g_hc[BB * HH];
__device__ float g_outbuf[BB * CEE];
__device__ float g_qsum[BB * CEE];
__device__ float g_imgf[BB * CEE];
__device__ float g_comb[BB * CEE];
__device__ float g_last[BB * (CEE + RWRW)];
__device__ float g_fc1[BB * ANSN];

// ---------------- helpers ----------------
__device__ __forceinline__ float sigf(float x) { return 1.0f / (1.0f + expf(-x)); }
__device__ __forceinline__ float softplusf(float x) {
    return fmaxf(x, 0.0f) + log1pf(expf(-fabsf(x)));
}
__device__ __forceinline__ float blk_max(float v, volatile float* red, int tid) {
    red[tid] = v; __syncthreads();
    for (int s = 128; s > 0; s >>= 1) {
        if (tid < s) red[tid] = fmaxf((float)red[tid], (float)red[tid + s]);
        __syncthreads();
    }
    float r = red[0]; __syncthreads();
    return r;
}
__device__ __forceinline__ float blk_sum(float v, volatile float* red, int tid) {
    red[tid] = v; __syncthreads();
    for (int s = 128; s > 0; s >>= 1) {
        if (tid < s) red[tid] = (float)red[tid] + (float)red[tid + s];
        __syncthreads();
    }
    float r = red[0]; __syncthreads();
    return r;
}

// ---------------- misc kernels ----------------
__global__ void k_zero(float* p, int n) {
    int i = blockIdx.x * blockDim.x + threadIdx.x;
    if (i < n) p[i] = 0.0f;
}

__global__ void k_embed(const int* __restrict__ qst, const float* __restrict__ emb) {
    int i = blockIdx.x * blockDim.x + threadIdx.x;
    if (i >= BB * TT * EE) return;
    int e = i % EE;
    int bt = i / EE;
    int tok = qst[bt];
    g_qv[i] = tanhf(emb[(size_t)tok * EE + e]);
}

// ---------------- GEMM microkernel: 16(M) x 64(N) tile, 256 threads ----------------
__device__ __forceinline__ void gemm_tile16x64(
    const float* __restrict__ A, const float* __restrict__ W,
    int K, int lda, int Nout, float* __restrict__ C) {
    __shared__ __align__(16) float As[16][17];
    __shared__ __align__(16) float Ws[16][68];
    int tid = threadIdx.x;
    int tx = tid & 31;
    int ty = tid >> 5;
    int col0 = blockIdx.x * 64;
    int row0 = blockIdx.y * 16;
    float a00 = 0, a01 = 0, a10 = 0, a11 = 0;
    bool vec4 = ((Nout & 3) == 0);

    for (int k0 = 0; k0 < K; k0 += 16) {
        {
            int r = tid >> 4, kk = tid & 15;
            int k = k0 + kk;
            As[r][kk] = (k < K) ? A[(size_t)(row0 + r) * lda + k] : 0.0f;
        }
        {
            int kk = tid >> 4;
            int cb = (tid & 15) * 4;
            int k = k0 + kk;
            if (k < K) {
                int c = col0 + cb;
                if (vec4 && c + 3 < Nout) {
                    float4 v = *(const float4*)&W[(size_t)k * Nout + c];
                    Ws[kk][cb] = v.x; Ws[kk][cb + 1] = v.y;
                    Ws[kk][cb + 2] = v.z; Ws[kk][cb + 3] = v.w;
                } else {
#pragma unroll
                    for (int u = 0; u < 4; u++)
                        Ws[kk][cb + u] = (c + u < Nout) ? W[(size_t)k * Nout + c + u] : 0.0f;
                }
            } else {
#pragma unroll
                for (int u = 0; u < 4; u++) Ws[kk][cb + u] = 0.0f;
            }
        }
        __syncthreads();
#pragma unroll
        for (int kk = 0; kk < 16; kk++) {
            float x0 = As[ty * 2][kk];
            float x1 = As[ty * 2 + 1][kk];
            float2 bv = *(const float2*)&Ws[kk][tx * 2];
            a00 += x0 * bv.x; a01 += x0 * bv.y;
            a10 += x1 * bv.x; a11 += x1 * bv.y;
        }
        __syncthreads();
    }
    int row = row0 + ty * 2;
    int c = col0 + tx * 2;
    if (c < Nout) {
        C[(size_t)row * Nout + c] = a00;
        C[(size_t)(row + 1) * Nout + c] = a10;
    }
    if (c + 1 < Nout) {
        C[(size_t)row * Nout + c + 1] = a01;
        C[(size_t)(row + 1) * Nout + c + 1] = a11;
    }
}

struct SegP {
    const float* A[4];
    const float* W[4];
    int K[4];
    int lda[4];
};

// split-K GEMM: grid.z = segment, writes partials to g_part
__global__ void gemm_sk(SegP p, int Nout) {
    int z = blockIdx.z;
    gemm_tile16x64(p.A[z], p.W[z], p.K[z], p.lda[z], Nout, g_part + (size_t)z * 64 * Nout);
}

// direct GEMM (precompute path, arbitrary M via grid.y)
__global__ void gemm_direct(const float* __restrict__ A, const float* __restrict__ W,
                            int K, int lda, int Nout, float* __restrict__ C) {
    gemm_tile16x64(A, W, K, lda, Nout, C);
}

// ---------------- reduction / pointwise kernels ----------------
__global__ void k_lstm(int nseg, int use_pre, int t, const float* __restrict__ bias) {
    int idx = blockIdx.x * blockDim.x + threadIdx.x;
    if (idx >= BB * HH) return;
    int b = idx >> 9;
    int j = idx & 511;
    float g[4];
#pragma unroll
    for (int q = 0; q < 4; q++) {
        int col = q * HH + j;
        float v = bias[col];
        if (use_pre) v += g_pre[((size_t)(b * TT + t)) * 2048 + col];
        for (int z = 0; z < nseg; z++) v += g_part[(size_t)z * 64 * 2048 + b * 2048 + col];
        g[q] = v;
    }
    float cc = sigf(g[1]) * g_state[OFF_C + idx] + sigf(g[0]) * tanhf(g[2]);
    float hh = sigf(g[3]) * tanhf(cc);
    g_state[OFF_C + idx] = cc;
    g_state[OFF_H + idx] = hh;
    g_hc[idx] = fminf(fmaxf(hh, -CLIPV), CLIPV);
}

__global__ void k_outred(int nseg, const float* __restrict__ bias, int accum) {
    int idx = blockIdx.x * blockDim.x + threadIdx.x;
    if (idx >= BB * CEE) return;
    int b = idx >> 10;
    int j = idx & 1023;
    float v = bias[j];
    for (int z = 0; z < nseg; z++) v += g_part[(size_t)z * 64 * 1024 + b * 1024 + j];
    v = fminf(fmaxf(v, -CLIPV), CLIPV);
    g_outbuf[idx] = v;
    if (accum) g_qsum[idx] += v;
}

__global__ void k_red(int nseg, int Nout, const float* __restrict__ bias,
                      float* __restrict__ out, int act) {
    int idx = blockIdx.x * blockDim.x + threadIdx.x;
    if (idx >= 64 * Nout) return;
    int j = idx % Nout;
    float v = bias[j];
    for (int z = 0; z < nseg; z++) v += g_part[(size_t)z * 64 * Nout + idx];
    if (act == 2) v = tanhf(v);
    out[idx] = v;
}

__global__ void k_comb(const float* __restrict__ img_b) {
    __shared__ float red[256];
    int b = blockIdx.x;
    int tid = threadIdx.x;
    float s = 0;
    for (int j = tid; j < CEE; j += 256) {
        float v = img_b[j];
        for (int z = 0; z < 4; z++) v += g_part[(size_t)z * 64 * 1024 + b * 1024 + j];
        g_imgf[b * CEE + j] = v;
        s += v * v;
    }
    float tot = blk_sum(s, red, tid);
    float inv = rsqrtf(tot);
    for (int j = tid; j < CEE; j += 256) {
        float v = g_imgf[b * CEE + j] * inv;
        g_comb[b * CEE + j] = tanhf(v * g_qsum[b * CEE + j] * (1.0f / (float)TT));
    }
}

__global__ void k_last() {
    int idx = blockIdx.x * blockDim.x + threadIdx.x;
    if (idx >= BB * (CEE + RWRW)) return;
    int b = idx / (CEE + RWRW);
    int j = idx % (CEE + RWRW);
    float v = (j < CEE) ? g_outbuf[b * CEE + j] : g_state[OFF_RVEC + b * 256 + (j - CEE)];
    g_last[idx] = tanhf(v);
}

// ---------------- fused per-batch DNC memory kernel ----------------
__global__ void k_dnc(const float* __restrict__ bif) {
    __shared__ float wro[4][256];
    __shared__ float sh_rk[256];
    __shared__ float sh_wkey[64], sh_erase[64], sh_wvec[64];
    __shared__ float sh_rstr[4], sh_free[4];
    __shared__ float sh_mraw[12], sh_modes[12];
    __shared__ float sh_scal[4];   // 0 wstr, 1 allocg, 2 writeg, 3 wwsum
    __shared__ float sh_alloc[256], sh_ww[256];
    __shared__ float red[256];
    __shared__ float sv[256];
    __shared__ int   si[256];
    __shared__ float sc[256];
    __shared__ float bws[4][256], fws[4][256], crs[4][256], wsn[4][256];

    int b = blockIdx.x;
    int tid = threadIdx.x;

    // load old read weights
#pragma unroll
    for (int r = 0; r < 4; r++)
        wro[r][tid] = g_state[OFF_WR + b * 1024 + r * 256 + tid];

    // ---- Phase A: xi reduce + interface transforms ----
    for (int t = tid; t < IFTOT; t += 256) {
        float v = bif[t] + g_part[(size_t)0 * 64 * IFTOT + b * IFTOT + t]
                         + g_part[(size_t)1 * 64 * IFTOT + b * IFTOT + t];
        if (t < 256)       sh_rk[t] = tanhf(v);
        else if (t < 260)  sh_rstr[t - 256] = softplusf(v);
        else if (t < 324)  sh_wkey[t - 260] = tanhf(v);
        else if (t == 324) sh_scal[0] = softplusf(v);
        else if (t < 389)  sh_erase[t - 325] = sigf(v);
        else if (t < 453)  sh_wvec[t - 389] = tanhf(v);
        else if (t < 457)  sh_free[t - 453] = sigf(v);
        else if (t == 457) sh_scal[1] = sigf(v);
        else if (t == 458) sh_scal[2] = sigf(v);
        else               sh_mraw[t - 459] = v;
    }
    __syncthreads();
    if (tid < 4) {
        float v0 = sh_mraw[tid * 3], v1 = sh_mraw[tid * 3 + 1], v2 = sh_mraw[tid * 3 + 2];
        float m = fmaxf(v0, fmaxf(v1, v2));
        float e0 = expf(v0 - m), e1 = expf(v1 - m), e2 = expf(v2 - m);
        float s = e0 + e1 + e2;
        sh_modes[tid * 3] = e0 / s;
        sh_modes[tid * 3 + 1] = e1 / s;
        sh_modes[tid * 3 + 2] = e2 / s;
    }
    __syncthreads();

    // ---- Phase B: usage update + stable argsort + alloc ----
    float psi = 1.0f;
#pragma unroll
    for (int r = 0; r < 4; r++)
        psi *= 1.0f - sh_free[r] * wro[r][tid];
    float uo = g_state[OFF_USAGE + b * 256 + tid];
    float wo = g_state[OFF_WW + b * 256 + tid];
    float u = (uo + wo - uo * wo) * psi;
    g_state[OFF_USAGE + b * 256 + tid] = u;
    sv[tid] = u; si[tid] = tid;
    __syncthreads();
    for (int k = 2; k <= 256; k <<= 1) {
        for (int j = k >> 1; j > 0; j >>= 1) {
            int ixj = tid ^ j;
            if (ixj > tid) {
                float v1 = sv[tid], v2 = sv[ixj];
                int i1 = si[tid], i2 = si[ixj];
                bool up = ((tid & k) == 0);
                bool gt = (v1 > v2) || (v1 == v2 && i1 > i2);
                bool doswap = up ? gt : !gt;
                if (doswap) { sv[tid] = v2; sv[ixj] = v1; si[tid] = i2; si[ixj] = i1; }
            }
            __syncthreads();
        }
    }
    sc[tid] = sv[tid];
    __syncthreads();
    for (int off = 1; off < 256; off <<= 1) {
        float tval = (tid >= off) ? sc[tid - off] : 1.0f;
        __syncthreads();
        sc[tid] *= tval;
        __syncthreads();
    }
    float cpe = (tid == 0) ? 1.0f : sc[tid - 1];
    sh_alloc[si[tid]] = (1.0f - sv[tid]) * cpe;
    __syncthreads();

    // ---- Phase C: write content weights + ww + wwsum (OLD mem) ----
    float kn = 0;
#pragma unroll 8
    for (int w = 0; w < 64; w++) kn += sh_wkey[w] * sh_wkey[w];
    kn = sqrtf(kn) + EPSV;
    float dot = 0, mn0 = 0;
    size_t mbase = (size_t)OFF_MEM + (size_t)b * NN * WW;
#pragma unroll 8
    for (int w = 0; w < 64; w++) {
        float m = g_state[mbase + (size_t)tid * WW + w];
        dot += m * sh_wkey[w];
        mn0 += m * m;
    }
    float sim = sh_scal[0] * dot / ((sqrtf(mn0) + EPSV) * kn);
    float mx = blk_max(sim, red, tid);
    float e = expf(sim - mx);
    float sm = blk_sum(e, red, tid);
    float cwv = e / sm;
    float ag = sh_scal[1], wg = sh_scal[2];
    float wwv = wg * (ag * sh_alloc[tid] + (1.0f - ag) * cwv);
    sh_ww[tid] = wwv;
    g_state[OFF_WW + b * 256 + tid] = wwv;
    float wws = blk_sum(wwv, red, tid);
    if (tid == 0) sh_scal[3] = wws;
    __syncthreads();

    // ---- Phase D: memory update ----
    for (int i = tid; i < NN * WW; i += 256) {
        int n = i >> 6;
        int w = i & 63;
        float m = g_state[mbase + i];
        g_state[mbase + i] = m * (1.0f - sh_ww[n] * sh_erase[w]) + sh_ww[n] * sh_wvec[w];
    }

    // ---- Phase E: link update + fused bw + prec ----
    float bwa0 = 0, bwa1 = 0, bwa2 = 0, bwa3 = 0;
    float precj = g_state[OFF_PREC + b * 256 + tid];
    size_t lb = (size_t)OFF_LINK + (size_t)b * 65536;
    float wwj = sh_ww[tid];
#pragma unroll 4
    for (int p = 0; p < 256; p++) {
        float lold = g_state[lb + (size_t)p * 256 + tid];
        float wi = sh_ww[p];
        float ln = (p == tid) ? 0.0f : (1.0f - wi - wwj) * lold + wi * precj;
        g_state[lb + (size_t)p * 256 + tid] = ln;
        bwa0 += ln * wro[0][p];
        bwa1 += ln * wro[1][p];
        bwa2 += ln * wro[2][p];
        bwa3 += ln * wro[3][p];
    }
    bws[0][tid] = bwa0; bws[1][tid] = bwa1; bws[2][tid] = bwa2; bws[3][tid] = bwa3;
    g_state[OFF_PREC + b * 256 + tid] = (1.0f - sh_scal[3]) * precj + wwj;
    __syncthreads();

    // ---- Phase F: fw (new link, old wr) ----
    {
        int warp = tid >> 5, lane = tid & 31;
        for (int ib = 0; ib < 32; ib++) {
            int i = warp * 32 + ib;
            float acc[4] = {0, 0, 0, 0};
#pragma unroll
            for (int kk = 0; kk < 8; kk++) {
                int j = lane + kk * 32;
                float lv = g_state[lb + (size_t)i * 256 + j];
#pragma unroll
                for (int r = 0; r < 4; r++) acc[r] += lv * wro[r][j];
            }
#pragma unroll
            for (int r = 0; r < 4; r++) {
#pragma unroll
                for (int off = 16; off > 0; off >>= 1)
                    acc[r] += __shfl_xor_sync(0xffffffff, acc[r], off);
            }
            if (lane == 0) {
#pragma unroll
                for (int r = 0; r < 4; r++) fws[r][i] = acc[r];
            }
        }
    }
    __syncthreads();

    // ---- Phase G: read content weights (NEW mem) ----
    float kn2[4];
#pragma unroll
    for (int r = 0; r < 4; r++) {
        float s = 0;
#pragma unroll 8
        for (int w = 0; w < 64; w++) s += sh_rk[r * 64 + w] * sh_rk[r * 64 + w];
        kn2[r] = sqrtf(s) + EPSV;
    }
    float mn = 0;
    float dots[4] = {0, 0, 0, 0};
#pragma unroll 4
    for (int w = 0; w < 64; w++) {
        float m = g_state[mbase + (size_t)tid * WW + w];
        mn += m * m;
#pragma unroll
        for (int r = 0; r < 4; r++) dots[r] += m * sh_rk[r * 64 + w];
    }
    float mnorm = sqrtf(mn) + EPSV;
    for (int r = 0; r < 4; r++) {
        float simr = sh_rstr[r] * dots[r] / (mnorm * kn2[r]);
        float mxr = blk_max(simr, red, tid);
        float er = expf(simr - mxr);
        float smr = blk_sum(er, red, tid);
        crs[r][tid] = er / smr;
    }

    // ---- Phase H: wr update + rvec ----
#pragma unroll
    for (int r = 0; r < 4; r++) {
        float v = sh_modes[r * 3 + 0] * bws[r][tid]
                + sh_modes[r * 3 + 1] * crs[r][tid]
                + sh_modes[r * 3 + 2] * fws[r][tid];
        wsn[r][tid] = v;
        g_state[OFF_WR + b * 1024 + r * 256 + tid] = v;
    }
    __syncthreads();
    {
        int r2 = tid >> 6;
        int w = tid & 63;
        float acc = 0;
#pragma unroll 4
        for (int n = 0; n < 256; n++)
            acc += wsn[r2][n] * g_state[mbase + (size_t)n * 64 + w];
        g_state[OFF_RVEC + b * 256 + tid] = acc;
    }
}

// ---------------- host ----------------
struct HostPtrs {
    float* state;
};

static void dnc_step_q(float* S, int t,
                       const float* Wih, const float* Whh, const float* bgate,
                       const float* Wif, const float* bif,
                       const float* Wout, const float* bout) {
    // gates (pre has x part): segments rvec(256), h(256), h(256)
    SegP gp = {};
    gp.A[0] = S + OFF_RVEC; gp.W[0] = Wih + (size_t)EE * 2048; gp.K[0] = 256; gp.lda[0] = 256;
    gp.A[1] = S + OFF_H;    gp.W[1] = Whh;                      gp.K[1] = 256; gp.lda[1] = 512;
    gp.A[2] = S + OFF_H + 256; gp.W[2] = Whh + (size_t)256 * 2048; gp.K[2] = 256; gp.lda[2] = 512;
    gemm_sk<<<dim3(32, 4, 3), 256>>>(gp, 2048);
    k_lstm<<<(BB * HH + 255) / 256, 256>>>(3, 1, t, bgate);

    float* hc;
    cudaGetSymbolAddress((void**)&hc, g_hc);
    SegP xp = {};
    xp.A[0] = hc;       xp.W[0] = Wif;                      xp.K[0] = 256; xp.lda[0] = 512;
    xp.A[1] = hc + 256; xp.W[1] = Wif + (size_t)256 * IFTOT; xp.K[1] = 256; xp.lda[1] = 512;
    gemm_sk<<<dim3(8, 4, 2), 256>>>(xp, IFTOT);
    k_dnc<<<BB, 256>>>(bif);

    SegP op = {};
    op.A[0] = hc;            op.W[0] = Wout;                        op.K[0] = 256; op.lda[0] = 512;
    op.A[1] = hc + 256;      op.W[1] = Wout + (size_t)256 * CEE;    op.K[1] = 256; op.lda[1] = 512;
    op.A[2] = S + OFF_RVEC;  op.W[2] = Wout + (size_t)512 * CEE;    op.K[2] = 256; op.lda[2] = 256;
    gemm_sk<<<dim3(16, 4, 3), 256>>>(op, CEE);
    k_outred<<<(BB * CEE + 255) / 256, 256>>>(3, bout, 1);
}

static void dnc_step_c(float* S, const float* comb,
                       const float* Wih, const float* Whh, const float* bgate,
                       const float* Wif, const float* bif,
                       const float* Wout, const float* bout) {
    SegP gp = {};
    gp.A[0] = comb;        gp.W[0] = Wih;                        gp.K[0] = 512; gp.lda[0] = 1024;
    gp.A[1] = comb + 512;  gp.W[1] = Wih + (size_t)512 * 2048;   gp.K[1] = 512; gp.lda[1] = 1024;
    gp.A[2] = S + OFF_RVEC; gp.W[2] = Wih + (size_t)1024 * 2048; gp.K[2] = 256; gp.lda[2] = 256;
    gp.A[3] = S + OFF_H;   gp.W[3] = Whh;                        gp.K[3] = 512; gp.lda[3] = 512;
    gemm_sk<<<dim3(32, 4, 4), 256>>>(gp, 2048);
    k_lstm<<<(BB * HH + 255) / 256, 256>>>(4, 0, 0, bgate);

    float* hc;
    cudaGetSymbolAddress((void**)&hc, g_hc);
    SegP xp = {};
    xp.A[0] = hc;       xp.W[0] = Wif;                       xp.K[0] = 256; xp.lda[0] = 512;
    xp.A[1] = hc + 256; xp.W[1] = Wif + (size_t)256 * IFTOT; xp.K[1] = 256; xp.lda[1] = 512;
    gemm_sk<<<dim3(8, 4, 2), 256>>>(xp, IFTOT);
    k_dnc<<<BB, 256>>>(bif);

    SegP op = {};
    op.A[0] = hc;            op.W[0] = Wout;                     op.K[0] = 256; op.lda[0] = 512;
    op.A[1] = hc + 256;      op.W[1] = Wout + (size_t)256 * CEE; op.K[1] = 256; op.lda[1] = 512;
    op.A[2] = S + OFF_RVEC;  op.W[2] = Wout + (size_t)512 * CEE; op.K[2] = 256; op.lda[2] = 256;
    gemm_sk<<<dim3(16, 4, 3), 256>>>(op, CEE);
    k_outred<<<(BB * CEE + 255) / 256, 256>>>(3, bout, 0);
}

extern "C" void kernel_launch(void* const* d_in, const int* in_sizes, int n_in,
                              void* d_out, int out_size) {
    const float* img_feat = (const float*)d_in[0];
    const int*   qst      = (const int*)d_in[1];
    const float* emb      = (const float*)d_in[2];
    const float* img_W    = (const float*)d_in[3];
    const float* img_b    = (const float*)d_in[4];
    const float* q_Wih    = (const float*)d_in[5];
    const float* q_Whh    = (const float*)d_in[6];
    const float* q_b      = (const float*)d_in[7];
    const float* q_Wif    = (const float*)d_in[8];
    const float* q_bif    = (const float*)d_in[9];
    const float* q_Wout   = (const float*)d_in[10];
    const float* q_bout   = (const float*)d_in[11];
    const float* c_Wih    = (const float*)d_in[12];
    const float* c_Whh    = (const float*)d_in[13];
    const float* c_b      = (const float*)d_in[14];
    const float* c_Wif    = (const float*)d_in[15];
    const float* c_bif    = (const float*)d_in[16];
    const float* c_Wout   = (const float*)d_in[17];
    const float* c_bout   = (const float*)d_in[18];
    const float* fc1_W    = (const float*)d_in[19];
    const float* fc1_b    = (const float*)d_in[20];
    const float* fc2_W    = (const float*)d_in[21];
    const float* fc2_b    = (const float*)d_in[22];
    float* out = (float*)d_out;

    float *S, *qv, *pre, *qsum, *comb, *last, *fc1;
    cudaGetSymbolAddress((void**)&S, g_state);
    cudaGetSymbolAddress((void**)&qv, g_qv);
    cudaGetSymbolAddress((void**)&pre, g_pre);
    cudaGetSymbolAddress((void**)&qsum, g_qsum);
    cudaGetSymbolAddress((void**)&comb, g_comb);
    cudaGetSymbolAddress((void**)&last, g_last);
    cudaGetSymbolAddress((void**)&fc1, g_fc1);

    // zero state + qsum
    k_zero<<<(STATE_TOT + 255) / 256, 256>>>(S, STATE_TOT);
    k_zero<<<(BB * CEE + 255) / 256, 256>>>(qsum, BB * CEE);

    // question embedding + hoisted x@Wih_x for all timesteps  [1280 x 2048]
    k_embed<<<(BB * TT * EE + 255) / 256, 256>>>(qst, emb);
    gemm_direct<<<dim3(32, (BB * TT) / 16), 256>>>(qv, q_Wih, EE, EE, 2048, pre);

    // question DNC over T timesteps
    for (int t = 0; t < TT; t++)
        dnc_step_q(S, t, q_Wih, q_Whh, q_b, q_Wif, q_bif, q_Wout, q_bout);

    // image encoder (split-K 4) + combine
    {
        SegP ip = {};
        for (int z = 0; z < 4; z++) {
            ip.A[z] = img_feat + (size_t)z * 1024;
            ip.W[z] = img_W + (size_t)z * 1024 * CEE;
            ip.K[z] = 1024;
            ip.lda[z] = 4096;
        }
        gemm_sk<<<dim3(16, 4, 4), 256>>>(ip, CEE);
        k_comb<<<BB, 256>>>(img_b);
    }

    // controller DNC (fresh state)
    k_zero<<<(STATE_TOT + 255) / 256, 256>>>(S, STATE_TOT);
    dnc_step_c(S, comb, c_Wih, c_Whh, c_b, c_Wif, c_bif, c_Wout, c_bout);

    // tail: last -> fc1(tanh) -> fc2
    k_last<<<(BB * (CEE + RWRW) + 255) / 256, 256>>>();
    {
        SegP f1 = {};
        for (int z = 0; z < 4; z++) {
            f1.A[z] = last + (size_t)z * 320;
            f1.W[z] = fc1_W + (size_t)z * 320 * ANSN;
            f1.K[z] = 320;
            f1.lda[z] = CEE + RWRW;
        }
        gemm_sk<<<dim3(47, 4, 4), 256>>>(f1, ANSN);
        k_red<<<(64 * ANSN + 255) / 256, 256>>>(4, ANSN, fc1_b, fc1, 2);
    }
    {
        SegP f2 = {};
        for (int z = 0; z < 4; z++) {
            f2.A[z] = fc1 + (size_t)z * 750;
            f2.W[z] = fc2_W + (size_t)z * 750 * ANSN;
            f2.K[z] = 750;
            f2.lda[z] = ANSN;
        }
        gemm_sk<<<dim3(47, 4, 4), 256>>>(f2, ANSN);
        k_red<<<(64 * ANSN + 255) / 256, 256>>>(4, ANSN, fc2_b, out, 0);
    }
}